// round 15
// baseline (speedup 1.0000x reference)
#include <cuda_runtime.h>
#include <cuda_fp16.h>
#include <cstddef>
#include <cstdint>

// ---------------------------------------------------------------------------
// GeoDynamicLayer: out = x @ W^T, W = RK4(dU/dt = U A + G).
// Factored RK4 (24-dim row space) + single-pass fp16 HMMA GEMM
// (x, W rounded to fp16; fp32 accumulate; rel_err ~3e-4 < 1e-3).
// Round 15: round-9 base; f0_rk4 with 2 warps/row dot phase; expand 256 blocks.
// ---------------------------------------------------------------------------

__device__ float g_partial[256 * 512];
__device__ float g_ab[16];
__device__ float g_S[24 * 16];
__device__ float g_P[1024 * 24];
__device__ __half g_x16[32768 * 512];
__device__ __half g_W16[1024 * 512];

// ---------------- Stage 1: convert x -> fp16 + column partial sums ----------
__global__ void convert_reduce_k(const float* __restrict__ x) {
    int t = threadIdx.x;                 // 0..511 = column
    int rowStart = blockIdx.x * 128;
    const float* p = x + (size_t)rowStart * 512 + t;
    float s = 0.f;
    #pragma unroll 4
    for (int r = 0; r < 128; ++r) {
        float v = p[(size_t)r * 512];
        s += v;
        g_x16[(size_t)(rowStart + r) * 512 + t] = __float2half_rn(v);
    }
    g_partial[blockIdx.x * 512 + t] = s;
}

// ---------------- Stage 2: xbar, abar, bbar ---------------------------------
__global__ void finalize_ab_k(const float* __restrict__ Wa,
                              const float* __restrict__ Wb) {
    __shared__ float sx[512];
    int t = threadIdx.x;
    float s = 0.f;
    #pragma unroll 8
    for (int p = 0; p < 256; ++p) s += g_partial[p * 512 + t];
    s *= (1.0f / 32768.0f);
    sx[t] = s;
    __syncthreads();
    int w = t >> 5, lane = t & 31;
    const float* Wm = (w < 8) ? Wa : Wb;
    int r = w & 7;
    float acc = 0.f;
    #pragma unroll
    for (int q = 0; q < 16; ++q) {
        int i = lane + q * 32;
        acc += sx[i] * Wm[i * 8 + r];
    }
    #pragma unroll
    for (int off = 16; off; off >>= 1)
        acc += __shfl_xor_sync(0xffffffffu, acc, off);
    if (lane == 0) g_ab[w] = acc;
}

// ---------------- Stage 3: S (24x16) ----------------------------------------
__global__ void compute_S_k(const float* __restrict__ La,
                            const float* __restrict__ Ra,
                            const float* __restrict__ Rb) {
    int gw = (blockIdx.x * blockDim.x + threadIdx.x) >> 5;
    int lane = threadIdx.x & 31;
    if (gw >= 384) return;
    int k = gw >> 4, c = gw & 15;
    const float* Vk = (k < 8) ? La : ((k < 16) ? Ra : Rb);
    int kk = k & 7;
    const float* M = (c < 8) ? Ra : La;
    int r = c & 7;
    float acc = 0.f;
    #pragma unroll
    for (int q = 0; q < 16; ++q) {
        int i = lane + q * 32;
        acc += Vk[i * 8 + kk] * M[i * 8 + r];
    }
    #pragma unroll
    for (int off = 16; off; off >>= 1)
        acc += __shfl_xor_sync(0xffffffffu, acc, off);
    if (lane == 0) {
        float d = g_ab[r];
        g_S[k * 16 + c] = (c < 8) ? (-acc * d) : (acc * d);
    }
}

// ---------------- Stage 4+5 fused: F0 row (2 warps/row) + RK4 ---------------
// Block = 256 threads = 8 warps = 4 rows.  Warp pair (2r, 2r+1): each warp
// dots HALF the row (8 iterations); partials combined via smem; even warp
// builds f0 and runs RK4 while the odd warp retires.
__global__ void f0_rk4_k(const float* __restrict__ U0,
                         const float* __restrict__ La,
                         const float* __restrict__ Ra,
                         const float* __restrict__ Lb) {
    __shared__ float part[8][16];
    int t = threadIdx.x;
    int w = t >> 5, lane = t & 31;
    int rloc = w >> 1;                   // local row 0..3
    int h = w & 1;                       // half 0/1
    int row = blockIdx.x * 4 + rloc;
    const float* u = U0 + (size_t)row * 512;
    float accA[8] = {0, 0, 0, 0, 0, 0, 0, 0};
    float accR[8] = {0, 0, 0, 0, 0, 0, 0, 0};
    int base = h * 256;
    #pragma unroll
    for (int q = 0; q < 8; ++q) {
        int i = base + lane + q * 32;
        float uv = u[i];
        float4 la0 = *(const float4*)(La + i * 8);
        float4 la1 = *(const float4*)(La + i * 8 + 4);
        float4 ra0 = *(const float4*)(Ra + i * 8);
        float4 ra1 = *(const float4*)(Ra + i * 8 + 4);
        accA[0] += uv * la0.x; accA[1] += uv * la0.y;
        accA[2] += uv * la0.z; accA[3] += uv * la0.w;
        accA[4] += uv * la1.x; accA[5] += uv * la1.y;
        accA[6] += uv * la1.z; accA[7] += uv * la1.w;
        accR[0] += uv * ra0.x; accR[1] += uv * ra0.y;
        accR[2] += uv * ra0.z; accR[3] += uv * ra0.w;
        accR[4] += uv * ra1.x; accR[5] += uv * ra1.y;
        accR[6] += uv * ra1.z; accR[7] += uv * ra1.w;
    }
    #pragma unroll
    for (int off = 16; off; off >>= 1) {
        #pragma unroll
        for (int r = 0; r < 8; ++r) {
            accA[r] += __shfl_xor_sync(0xffffffffu, accA[r], off);
            accR[r] += __shfl_xor_sync(0xffffffffu, accR[r], off);
        }
    }
    // lanes 0..7 publish their accA[lane]/accR[lane] (static select)
    float pa = 0.f, pr = 0.f;
    #pragma unroll
    for (int r = 0; r < 8; ++r) {
        if (lane == r) { pa = accA[r]; pr = accR[r]; }
    }
    if (lane < 8) {
        part[w][lane] = pa;
        part[w][8 + lane] = pr;
    }
    __syncthreads();
    if (h) return;                        // odd warps done

    // even warp: combine halves, build f0 (lane c = component c)
    float f0 = 0.f;
    if (lane < 8) {
        float rA = part[w][8 + lane] + part[w + 1][8 + lane];
        f0 = -g_ab[lane] * rA;
    } else if (lane < 16) {
        float aA = part[w][lane - 8] + part[w + 1][lane - 8];
        f0 = g_ab[lane - 8] * aA;
    } else if (lane < 24 && row >= 512) {
        f0 = g_ab[8 + (lane - 16)] * Lb[(row - 512) * 8 + (lane - 16)];
    }

    float scol[24];
    #pragma unroll
    for (int k = 0; k < 24; ++k)
        scol[k] = (lane < 16) ? g_S[k * 16 + lane] : 0.f;
    float p[24];
    #pragma unroll
    for (int k = 0; k < 24; ++k) p[k] = 0.f;
    const float dt = 1.0f / 8.0f;
    for (int step = 0; step < 8; ++step) {
        float v[24], acc[24];
        #pragma unroll
        for (int k = 0; k < 24; ++k) v[k] = p[k];
        float kc = f0;
        #pragma unroll
        for (int k = 0; k < 24; ++k) kc += v[k] * scol[k];
        #pragma unroll
        for (int k = 0; k < 24; ++k) {
            float kf = __shfl_sync(0xffffffffu, kc, k);
            acc[k] = kf;
            v[k] = p[k] + 0.5f * dt * kf;
        }
        kc = f0;
        #pragma unroll
        for (int k = 0; k < 24; ++k) kc += v[k] * scol[k];
        #pragma unroll
        for (int k = 0; k < 24; ++k) {
            float kf = __shfl_sync(0xffffffffu, kc, k);
            acc[k] += 2.0f * kf;
            v[k] = p[k] + 0.5f * dt * kf;
        }
        kc = f0;
        #pragma unroll
        for (int k = 0; k < 24; ++k) kc += v[k] * scol[k];
        #pragma unroll
        for (int k = 0; k < 24; ++k) {
            float kf = __shfl_sync(0xffffffffu, kc, k);
            acc[k] += 2.0f * kf;
            v[k] = p[k] + dt * kf;
        }
        kc = f0;
        #pragma unroll
        for (int k = 0; k < 24; ++k) kc += v[k] * scol[k];
        #pragma unroll
        for (int k = 0; k < 24; ++k) {
            float kf = __shfl_sync(0xffffffffu, kc, k);
            acc[k] += kf;
        }
        #pragma unroll
        for (int k = 0; k < 24; ++k) p[k] += (dt / 6.0f) * acc[k];
    }
    if (lane < 24) g_P[row * 24 + lane] = p[lane];
}

// ---------------- Stage 6: W = U0 + P V2^T -> fp16 (256 blocks x 4 rows) ----
__global__ void expand_W_k(const float* __restrict__ U0,
                           const float* __restrict__ La,
                           const float* __restrict__ Ra,
                           const float* __restrict__ Rb) {
    __shared__ float sP[4 * 24];
    int t = threadIdx.x;
    int o0 = blockIdx.x * 4;
    if (t < 96) sP[t] = g_P[o0 * 24 + t];
    __syncthreads();
    #pragma unroll
    for (int half = 0; half < 2; ++half) {
        int i = t + half * 256;
        float v2[24];
        float4 q;
        q = *(const float4*)(La + i * 8);
        v2[0] = q.x; v2[1] = q.y; v2[2] = q.z; v2[3] = q.w;
        q = *(const float4*)(La + i * 8 + 4);
        v2[4] = q.x; v2[5] = q.y; v2[6] = q.z; v2[7] = q.w;
        q = *(const float4*)(Ra + i * 8);
        v2[8] = q.x; v2[9] = q.y; v2[10] = q.z; v2[11] = q.w;
        q = *(const float4*)(Ra + i * 8 + 4);
        v2[12] = q.x; v2[13] = q.y; v2[14] = q.z; v2[15] = q.w;
        q = *(const float4*)(Rb + i * 8);
        v2[16] = q.x; v2[17] = q.y; v2[18] = q.z; v2[19] = q.w;
        q = *(const float4*)(Rb + i * 8 + 4);
        v2[20] = q.x; v2[21] = q.y; v2[22] = q.z; v2[23] = q.w;
        #pragma unroll
        for (int r = 0; r < 4; ++r) {
            float accv = U0[(size_t)(o0 + r) * 512 + i];
            #pragma unroll
            for (int k = 0; k < 24; ++k) accv += sP[r * 24 + k] * v2[k];
            g_W16[(size_t)(o0 + r) * 512 + i] = __float2half_rn(accv);
        }
    }
}

// ---------------- Stage 7: fp16 HMMA GEMM  out = x @ W^T --------------------
// 3-stage cp.async pipeline (60KB dynamic smem), ONE __syncthreads per chunk.
#define CP16(sa, ga) \
    asm volatile("cp.async.cg.shared.global [%0], [%1], 16;\n" :: "r"(sa), "l"(ga))

__device__ __forceinline__ void ldm_x4(uint32_t& r0, uint32_t& r1,
                                       uint32_t& r2, uint32_t& r3, uint32_t a) {
    asm volatile("ldmatrix.sync.aligned.m8n8.x4.shared.b16 {%0,%1,%2,%3}, [%4];"
                 : "=r"(r0), "=r"(r1), "=r"(r2), "=r"(r3) : "r"(a));
}

__device__ __forceinline__ void mma16816(float* c, const uint32_t* a,
                                         const uint32_t* b) {
    asm volatile(
        "mma.sync.aligned.m16n8k16.row.col.f32.f16.f16.f32 "
        "{%0,%1,%2,%3}, {%4,%5,%6,%7}, {%8,%9}, {%0,%1,%2,%3};"
        : "+f"(c[0]), "+f"(c[1]), "+f"(c[2]), "+f"(c[3])
        : "r"(a[0]), "r"(a[1]), "r"(a[2]), "r"(a[3]), "r"(b[0]), "r"(b[1]));
}

__global__ __launch_bounds__(256) void gemm_tc_k(float* __restrict__ out) {
    extern __shared__ __align__(16) char dynsm[];
    uint32_t base = (uint32_t)__cvta_generic_to_shared(dynsm);

    int tid = threadIdx.x;
    int lane = tid & 31;
    int w = tid >> 5;
    int wm = (w & 3) * 32;
    int wn = (w >> 2) * 64;
    int bm = blockIdx.y * 128;
    int bn = blockIdx.x * 128;

    float c[2][8][4];
    #pragma unroll
    for (int mi = 0; mi < 2; ++mi)
        #pragma unroll
        for (int ni = 0; ni < 8; ++ni)
            #pragma unroll
            for (int q = 0; q < 4; ++q) c[mi][ni][q] = 0.f;

    int lr0 = tid >> 2;
    int lu = tid & 3;

    auto issue_chunk = [&](int i) {
        int st = i % 3;
        uint32_t sA = base + st * 20480;
        uint32_t sB = sA + 10240;
        int ko = i << 5;
        #pragma unroll
        for (int j = 0; j < 2; ++j) {
            int r = lr0 + j * 64;
            const __half* ga = g_x16 + (size_t)(bm + r) * 512 + ko + lu * 8;
            CP16(sA + ((r * 5 + lu) << 4), ga);
            const __half* gb = g_W16 + (size_t)(bn + r) * 512 + ko + lu * 8;
            CP16(sB + ((r * 5 + lu) << 4), gb);
        }
        asm volatile("cp.async.commit_group;\n" ::);
    };

    issue_chunk(0);
    issue_chunk(1);

    int mg = lane >> 3, rr = lane & 7;

    for (int i = 0; i < 16; ++i) {
        if (i < 15) asm volatile("cp.async.wait_group 1;\n" ::);
        else        asm volatile("cp.async.wait_group 0;\n" ::);
        __syncthreads();
        if (i + 2 < 16) issue_chunk(i + 2);

        int st = i % 3;
        uint32_t sA = base + st * 20480;
        uint32_t sB = sA + 10240;
        #pragma unroll
        for (int ks = 0; ks < 2; ++ks) {
            uint32_t a[2][4];
            #pragma unroll
            for (int mi = 0; mi < 2; ++mi) {
                int row = wm + mi * 16 + (mg & 1) * 8 + rr;
                int ku = ks * 2 + (mg >> 1);
                ldm_x4(a[mi][0], a[mi][1], a[mi][2], a[mi][3],
                       sA + ((row * 5 + ku) << 4));
            }
            uint32_t b[8][2];
            #pragma unroll
            for (int j = 0; j < 4; ++j) {
                int row = wn + j * 16 + (mg >> 1) * 8 + rr;
                int ku = ks * 2 + (mg & 1);
                ldm_x4(b[2 * j][0], b[2 * j][1], b[2 * j + 1][0], b[2 * j + 1][1],
                       sB + ((row * 5 + ku) << 4));
            }
            #pragma unroll
            for (int mi = 0; mi < 2; ++mi)
                #pragma unroll
                for (int ni = 0; ni < 8; ++ni)
                    mma16816(c[mi][ni], a[mi], b[ni]);
        }
    }

    int gid = lane >> 2, tig = lane & 3;
    #pragma unroll
    for (int mi = 0; mi < 2; ++mi) {
        #pragma unroll
        for (int ni = 0; ni < 8; ++ni) {
            int row0 = bm + wm + mi * 16 + gid;
            int col = bn + wn + ni * 8 + tig * 2;
            float2* p0 = (float2*)(out + (size_t)row0 * 1024 + col);
            *p0 = make_float2(c[mi][ni][0], c[mi][ni][1]);
            float2* p1 = (float2*)(out + (size_t)(row0 + 8) * 1024 + col);
            *p1 = make_float2(c[mi][ni][2], c[mi][ni][3]);
        }
    }
}

// ---------------------------------------------------------------------------
extern "C" void kernel_launch(void* const* d_in, const int* in_sizes, int n_in,
                              void* d_out, int out_size) {
    const float* x  = (const float*)d_in[0];
    const float* U0 = (const float*)d_in[1];
    const float* Wa = (const float*)d_in[2];
    const float* La = (const float*)d_in[3];
    const float* Ra = (const float*)d_in[4];
    const float* Wb = (const float*)d_in[5];
    const float* Lb = (const float*)d_in[6];
    const float* Rb = (const float*)d_in[7];
    float* out = (float*)d_out;
    (void)in_sizes; (void)n_in; (void)out_size;

    static int smem_set = 0;
    const int dyn_smem = 3 * 20480;      // 60 KB
    if (!smem_set) {
        cudaFuncSetAttribute(gemm_tc_k,
                             cudaFuncAttributeMaxDynamicSharedMemorySize,
                             dyn_smem);
        smem_set = 1;
    }

    convert_reduce_k<<<256, 512>>>(x);
    finalize_ab_k<<<1, 512>>>(Wa, Wb);
    compute_S_k<<<48, 256>>>(La, Ra, Rb);
    f0_rk4_k<<<256, 256>>>(U0, La, Ra, Lb);
    expand_W_k<<<256, 256>>>(U0, La, Ra, Rb);
    gemm_tc_k<<<dim3(8, 256), 256, dyn_smem>>>(out);
}

// round 16
// speedup vs baseline: 1.0131x; 1.0131x over previous
#include <cuda_runtime.h>
#include <cuda_fp16.h>
#include <cstddef>
#include <cstdint>

// ---------------------------------------------------------------------------
// GeoDynamicLayer: out = x @ W^T, W = RK4(dU/dt = U A + G).
// Factored RK4 (24-dim row space) + single-pass fp16 HMMA GEMM.
// Round 16: two-stream graph (fork/join via events): S-dots and U0-dots
// (independent of x) overlap with the convert pass; RK4 keeps only the
// shfl chain.  Arithmetic identical to round 9 (rel_err 2.9354e-4).
// ---------------------------------------------------------------------------

__device__ float g_partial[256 * 512];
__device__ float g_ab[16];
__device__ float g_S[24 * 16];     // sign applied, ab-scaling deferred
__device__ float g_F0d[1024 * 16]; // [0:8)=U0.La dots, [8:16)=U0.Ra dots
__device__ float g_P[1024 * 24];
__device__ __half g_x16[32768 * 512];
__device__ __half g_W16[1024 * 512];

// ---------------- Stage 1 (s0): convert x -> fp16 + column partial sums -----
__global__ void convert_reduce_k(const float* __restrict__ x) {
    int t = threadIdx.x;                 // 0..511 = column
    int rowStart = blockIdx.x * 128;
    const float* p = x + (size_t)rowStart * 512 + t;
    float s = 0.f;
    #pragma unroll 4
    for (int r = 0; r < 128; ++r) {
        float v = p[(size_t)r * 512];
        s += v;
        g_x16[(size_t)(rowStart + r) * 512 + t] = __float2half_rn(v);
    }
    g_partial[blockIdx.x * 512 + t] = s;
}

// ---------------- Stage 2 (s0): xbar, abar, bbar ----------------------------
__global__ void finalize_ab_k(const float* __restrict__ Wa,
                              const float* __restrict__ Wb) {
    __shared__ float sx[512];
    int t = threadIdx.x;
    float s = 0.f;
    #pragma unroll 8
    for (int p = 0; p < 256; ++p) s += g_partial[p * 512 + t];
    s *= (1.0f / 32768.0f);
    sx[t] = s;
    __syncthreads();
    int w = t >> 5, lane = t & 31;
    const float* Wm = (w < 8) ? Wa : Wb;
    int r = w & 7;
    float acc = 0.f;
    #pragma unroll
    for (int q = 0; q < 16; ++q) {
        int i = lane + q * 32;
        acc += sx[i] * Wm[i * 8 + r];
    }
    #pragma unroll
    for (int off = 16; off; off >>= 1)
        acc += __shfl_xor_sync(0xffffffffu, acc, off);
    if (lane == 0) g_ab[w] = acc;
}

// ---------------- Stage A (s2): S dots, sign applied, NO ab scaling ---------
__global__ void compute_Sraw_k(const float* __restrict__ La,
                               const float* __restrict__ Ra,
                               const float* __restrict__ Rb) {
    int gw = (blockIdx.x * blockDim.x + threadIdx.x) >> 5;
    int lane = threadIdx.x & 31;
    if (gw >= 384) return;
    int k = gw >> 4, c = gw & 15;
    const float* Vk = (k < 8) ? La : ((k < 16) ? Ra : Rb);
    int kk = k & 7;
    const float* M = (c < 8) ? Ra : La;
    int r = c & 7;
    float acc = 0.f;
    #pragma unroll
    for (int q = 0; q < 16; ++q) {
        int i = lane + q * 32;
        acc += Vk[i * 8 + kk] * M[i * 8 + r];
    }
    #pragma unroll
    for (int off = 16; off; off >>= 1)
        acc += __shfl_xor_sync(0xffffffffu, acc, off);
    if (lane == 0)
        g_S[k * 16 + c] = (c < 8) ? -acc : acc;
    (void)r;
}

// ---------------- Stage B (s2): U0 dot products (warp per row) --------------
__global__ void f0dot_k(const float* __restrict__ U0,
                        const float* __restrict__ La,
                        const float* __restrict__ Ra) {
    int w = (blockIdx.x * blockDim.x + threadIdx.x) >> 5;   // row 0..1023
    int lane = threadIdx.x & 31;
    const float* u = U0 + (size_t)w * 512;
    float accA[8] = {0, 0, 0, 0, 0, 0, 0, 0};
    float accR[8] = {0, 0, 0, 0, 0, 0, 0, 0};
    #pragma unroll
    for (int q = 0; q < 16; ++q) {
        int i = lane + q * 32;
        float uv = u[i];
        float4 la0 = *(const float4*)(La + i * 8);
        float4 la1 = *(const float4*)(La + i * 8 + 4);
        float4 ra0 = *(const float4*)(Ra + i * 8);
        float4 ra1 = *(const float4*)(Ra + i * 8 + 4);
        accA[0] += uv * la0.x; accA[1] += uv * la0.y;
        accA[2] += uv * la0.z; accA[3] += uv * la0.w;
        accA[4] += uv * la1.x; accA[5] += uv * la1.y;
        accA[6] += uv * la1.z; accA[7] += uv * la1.w;
        accR[0] += uv * ra0.x; accR[1] += uv * ra0.y;
        accR[2] += uv * ra0.z; accR[3] += uv * ra0.w;
        accR[4] += uv * ra1.x; accR[5] += uv * ra1.y;
        accR[6] += uv * ra1.z; accR[7] += uv * ra1.w;
    }
    #pragma unroll
    for (int off = 16; off; off >>= 1) {
        #pragma unroll
        for (int r = 0; r < 8; ++r) {
            accA[r] += __shfl_xor_sync(0xffffffffu, accA[r], off);
            accR[r] += __shfl_xor_sync(0xffffffffu, accR[r], off);
        }
    }
    float outv = 0.f;
    #pragma unroll
    for (int r = 0; r < 8; ++r) {
        if (lane == r)     outv = accA[r];
        if (lane == r + 8) outv = accR[r];
    }
    if (lane < 16) g_F0d[w * 16 + lane] = outv;
}

// ---------------- Stage 3 (s0, post-join): RK4 in coefficient space ---------
__global__ void rk4_k(const float* __restrict__ Lb) {
    int row = (blockIdx.x * blockDim.x + threadIdx.x) >> 5;  // 0..1023
    int lane = threadIdx.x & 31;
    // f0: col c<8 = -ab[c]*accR[c]; col 8+r = ab[r]*accA[r]; col 16+r = forcing
    float f0 = 0.f;
    if (lane < 8)
        f0 = -g_ab[lane] * g_F0d[row * 16 + 8 + lane];
    else if (lane < 16)
        f0 = g_ab[lane - 8] * g_F0d[row * 16 + (lane - 8)];
    else if (lane < 24 && row >= 512)
        f0 = g_ab[8 + (lane - 16)] * Lb[(row - 512) * 8 + (lane - 16)];

    float scol[24];
    float dscale = g_ab[lane & 7];
    #pragma unroll
    for (int k = 0; k < 24; ++k)
        scol[k] = (lane < 16) ? g_S[k * 16 + lane] * dscale : 0.f;
    float p[24];
    #pragma unroll
    for (int k = 0; k < 24; ++k) p[k] = 0.f;
    const float dt = 1.0f / 8.0f;
    for (int step = 0; step < 8; ++step) {
        float v[24], acc[24];
        #pragma unroll
        for (int k = 0; k < 24; ++k) v[k] = p[k];
        float kc = f0;
        #pragma unroll
        for (int k = 0; k < 24; ++k) kc += v[k] * scol[k];
        #pragma unroll
        for (int k = 0; k < 24; ++k) {
            float kf = __shfl_sync(0xffffffffu, kc, k);
            acc[k] = kf;
            v[k] = p[k] + 0.5f * dt * kf;
        }
        kc = f0;
        #pragma unroll
        for (int k = 0; k < 24; ++k) kc += v[k] * scol[k];
        #pragma unroll
        for (int k = 0; k < 24; ++k) {
            float kf = __shfl_sync(0xffffffffu, kc, k);
            acc[k] += 2.0f * kf;
            v[k] = p[k] + 0.5f * dt * kf;
        }
        kc = f0;
        #pragma unroll
        for (int k = 0; k < 24; ++k) kc += v[k] * scol[k];
        #pragma unroll
        for (int k = 0; k < 24; ++k) {
            float kf = __shfl_sync(0xffffffffu, kc, k);
            acc[k] += 2.0f * kf;
            v[k] = p[k] + dt * kf;
        }
        kc = f0;
        #pragma unroll
        for (int k = 0; k < 24; ++k) kc += v[k] * scol[k];
        #pragma unroll
        for (int k = 0; k < 24; ++k) {
            float kf = __shfl_sync(0xffffffffu, kc, k);
            acc[k] += kf;
        }
        #pragma unroll
        for (int k = 0; k < 24; ++k) p[k] += (dt / 6.0f) * acc[k];
    }
    if (lane < 24) g_P[row * 24 + lane] = p[lane];
}

// ---------------- Stage 4 (s0): W = U0 + P V2^T  -> fp16 --------------------
__global__ void expand_W_k(const float* __restrict__ U0,
                           const float* __restrict__ La,
                           const float* __restrict__ Ra,
                           const float* __restrict__ Rb) {
    __shared__ float sP[8 * 24];
    int t = threadIdx.x;
    int o0 = blockIdx.x * 8;
    if (t < 192) sP[t] = g_P[o0 * 24 + t];
    __syncthreads();
    #pragma unroll
    for (int half = 0; half < 2; ++half) {
        int i = t + half * 256;
        float v2[24];
        float4 q;
        q = *(const float4*)(La + i * 8);
        v2[0] = q.x; v2[1] = q.y; v2[2] = q.z; v2[3] = q.w;
        q = *(const float4*)(La + i * 8 + 4);
        v2[4] = q.x; v2[5] = q.y; v2[6] = q.z; v2[7] = q.w;
        q = *(const float4*)(Ra + i * 8);
        v2[8] = q.x; v2[9] = q.y; v2[10] = q.z; v2[11] = q.w;
        q = *(const float4*)(Ra + i * 8 + 4);
        v2[12] = q.x; v2[13] = q.y; v2[14] = q.z; v2[15] = q.w;
        q = *(const float4*)(Rb + i * 8);
        v2[16] = q.x; v2[17] = q.y; v2[18] = q.z; v2[19] = q.w;
        q = *(const float4*)(Rb + i * 8 + 4);
        v2[20] = q.x; v2[21] = q.y; v2[22] = q.z; v2[23] = q.w;
        #pragma unroll
        for (int r = 0; r < 8; ++r) {
            float accv = U0[(size_t)(o0 + r) * 512 + i];
            #pragma unroll
            for (int k = 0; k < 24; ++k) accv += sP[r * 24 + k] * v2[k];
            g_W16[(size_t)(o0 + r) * 512 + i] = __float2half_rn(accv);
        }
    }
}

// ---------------- Stage 5 (s0): fp16 HMMA GEMM  out = x @ W^T ---------------
#define CP16(sa, ga) \
    asm volatile("cp.async.cg.shared.global [%0], [%1], 16;\n" :: "r"(sa), "l"(ga))

__device__ __forceinline__ void ldm_x4(uint32_t& r0, uint32_t& r1,
                                       uint32_t& r2, uint32_t& r3, uint32_t a) {
    asm volatile("ldmatrix.sync.aligned.m8n8.x4.shared.b16 {%0,%1,%2,%3}, [%4];"
                 : "=r"(r0), "=r"(r1), "=r"(r2), "=r"(r3) : "r"(a));
}

__device__ __forceinline__ void mma16816(float* c, const uint32_t* a,
                                         const uint32_t* b) {
    asm volatile(
        "mma.sync.aligned.m16n8k16.row.col.f32.f16.f16.f32 "
        "{%0,%1,%2,%3}, {%4,%5,%6,%7}, {%8,%9}, {%0,%1,%2,%3};"
        : "+f"(c[0]), "+f"(c[1]), "+f"(c[2]), "+f"(c[3])
        : "r"(a[0]), "r"(a[1]), "r"(a[2]), "r"(a[3]), "r"(b[0]), "r"(b[1]));
}

__global__ __launch_bounds__(256) void gemm_tc_k(float* __restrict__ out) {
    extern __shared__ __align__(16) char dynsm[];
    uint32_t base = (uint32_t)__cvta_generic_to_shared(dynsm);

    int tid = threadIdx.x;
    int lane = tid & 31;
    int w = tid >> 5;
    int wm = (w & 3) * 32;
    int wn = (w >> 2) * 64;
    int bm = blockIdx.y * 128;
    int bn = blockIdx.x * 128;

    float c[2][8][4];
    #pragma unroll
    for (int mi = 0; mi < 2; ++mi)
        #pragma unroll
        for (int ni = 0; ni < 8; ++ni)
            #pragma unroll
            for (int q = 0; q < 4; ++q) c[mi][ni][q] = 0.f;

    int lr0 = tid >> 2;
    int lu = tid & 3;

    auto issue_chunk = [&](int i) {
        int st = i % 3;
        uint32_t sA = base + st * 20480;
        uint32_t sB = sA + 10240;
        int ko = i << 5;
        #pragma unroll
        for (int j = 0; j < 2; ++j) {
            int r = lr0 + j * 64;
            const __half* ga = g_x16 + (size_t)(bm + r) * 512 + ko + lu * 8;
            CP16(sA + ((r * 5 + lu) << 4), ga);
            const __half* gb = g_W16 + (size_t)(bn + r) * 512 + ko + lu * 8;
            CP16(sB + ((r * 5 + lu) << 4), gb);
        }
        asm volatile("cp.async.commit_group;\n" ::);
    };

    issue_chunk(0);
    issue_chunk(1);

    int mg = lane >> 3, rr = lane & 7;

    for (int i = 0; i < 16; ++i) {
        if (i < 15) asm volatile("cp.async.wait_group 1;\n" ::);
        else        asm volatile("cp.async.wait_group 0;\n" ::);
        __syncthreads();
        if (i + 2 < 16) issue_chunk(i + 2);

        int st = i % 3;
        uint32_t sA = base + st * 20480;
        uint32_t sB = sA + 10240;
        #pragma unroll
        for (int ks = 0; ks < 2; ++ks) {
            uint32_t a[2][4];
            #pragma unroll
            for (int mi = 0; mi < 2; ++mi) {
                int row = wm + mi * 16 + (mg & 1) * 8 + rr;
                int ku = ks * 2 + (mg >> 1);
                ldm_x4(a[mi][0], a[mi][1], a[mi][2], a[mi][3],
                       sA + ((row * 5 + ku) << 4));
            }
            uint32_t b[8][2];
            #pragma unroll
            for (int j = 0; j < 4; ++j) {
                int row = wn + j * 16 + (mg >> 1) * 8 + rr;
                int ku = ks * 2 + (mg & 1);
                ldm_x4(b[2 * j][0], b[2 * j][1], b[2 * j + 1][0], b[2 * j + 1][1],
                       sB + ((row * 5 + ku) << 4));
            }
            #pragma unroll
            for (int mi = 0; mi < 2; ++mi)
                #pragma unroll
                for (int ni = 0; ni < 8; ++ni)
                    mma16816(c[mi][ni], a[mi], b[ni]);
        }
    }

    int gid = lane >> 2, tig = lane & 3;
    #pragma unroll
    for (int mi = 0; mi < 2; ++mi) {
        #pragma unroll
        for (int ni = 0; ni < 8; ++ni) {
            int row0 = bm + wm + mi * 16 + gid;
            int col = bn + wn + ni * 8 + tig * 2;
            float2* p0 = (float2*)(out + (size_t)row0 * 1024 + col);
            *p0 = make_float2(c[mi][ni][0], c[mi][ni][1]);
            float2* p1 = (float2*)(out + (size_t)(row0 + 8) * 1024 + col);
            *p1 = make_float2(c[mi][ni][2], c[mi][ni][3]);
        }
    }
}

// ---------------------------------------------------------------------------
extern "C" void kernel_launch(void* const* d_in, const int* in_sizes, int n_in,
                              void* d_out, int out_size) {
    const float* x  = (const float*)d_in[0];
    const float* U0 = (const float*)d_in[1];
    const float* Wa = (const float*)d_in[2];
    const float* La = (const float*)d_in[3];
    const float* Ra = (const float*)d_in[4];
    const float* Wb = (const float*)d_in[5];
    const float* Lb = (const float*)d_in[6];
    const float* Rb = (const float*)d_in[7];
    float* out = (float*)d_out;
    (void)in_sizes; (void)n_in; (void)out_size;

    static cudaStream_t s2 = nullptr;
    static cudaEvent_t eFork = nullptr, eJoin = nullptr;
    static int smem_set = 0;
    const int dyn_smem = 3 * 20480;      // 60 KB
    if (!smem_set) {
        cudaFuncSetAttribute(gemm_tc_k,
                             cudaFuncAttributeMaxDynamicSharedMemorySize,
                             dyn_smem);
        cudaStreamCreateWithFlags(&s2, cudaStreamNonBlocking);
        cudaEventCreateWithFlags(&eFork, cudaEventDisableTiming);
        cudaEventCreateWithFlags(&eJoin, cudaEventDisableTiming);
        smem_set = 1;
    }

    // fork: side stream runs x-independent dot kernels
    cudaEventRecord(eFork, 0);
    cudaStreamWaitEvent(s2, eFork, 0);
    compute_Sraw_k<<<48, 256, 0, s2>>>(La, Ra, Rb);
    f0dot_k<<<128, 256, 0, s2>>>(U0, La, Ra);
    cudaEventRecord(eJoin, s2);

    // main stream: x-dependent chain
    convert_reduce_k<<<256, 512>>>(x);
    finalize_ab_k<<<1, 512>>>(Wa, Wb);

    // join, then the dependent tail
    cudaStreamWaitEvent(0, eJoin, 0);
    rk4_k<<<128, 256>>>(Lb);
    expand_W_k<<<128, 256>>>(U0, La, Ra, Rb);
    gemm_tc_k<<<dim3(8, 256), 256, dyn_smem>>>(out);
}

// round 17
// speedup vs baseline: 1.0475x; 1.0339x over previous
#include <cuda_runtime.h>
#include <cuda_fp16.h>
#include <cstddef>
#include <cstdint>

// ---------------------------------------------------------------------------
// GeoDynamicLayer: out = x @ W^T, W = RK4(dU/dt = U A + G).
// Factored RK4 (24-dim row space) + single-pass fp16 HMMA GEMM.
// Round 17: round-16 fork/join structure + TREE REDUCTION for xbar
// (finalize_ab was 23.4us single-block latency; now 32-block tree + short
// finalize).  Arithmetic otherwise identical (rel_err ~2.9354e-4).
// ---------------------------------------------------------------------------

__device__ float g_partial[256 * 512];
__device__ float g_partial2[32 * 512];
__device__ float g_ab[16];
__device__ float g_S[24 * 16];     // sign applied, ab-scaling deferred
__device__ float g_F0d[1024 * 16]; // [0:8)=U0.La dots, [8:16)=U0.Ra dots
__device__ float g_P[1024 * 24];
__device__ __half g_x16[32768 * 512];
__device__ __half g_W16[1024 * 512];

// ---------------- Stage 1 (s0): convert x -> fp16 + column partial sums -----
__global__ void convert_reduce_k(const float* __restrict__ x) {
    int t = threadIdx.x;                 // 0..511 = column
    int rowStart = blockIdx.x * 128;
    const float* p = x + (size_t)rowStart * 512 + t;
    float s = 0.f;
    #pragma unroll 4
    for (int r = 0; r < 128; ++r) {
        float v = p[(size_t)r * 512];
        s += v;
        g_x16[(size_t)(rowStart + r) * 512 + t] = __float2half_rn(v);
    }
    g_partial[blockIdx.x * 512 + t] = s;
}

// ---------------- Stage 1b (s0): tree-reduce 256 partials -> 32 -------------
__global__ void reduce8_k() {
    int t = threadIdx.x;
    int b = blockIdx.x;                  // 0..31
    float s = 0.f;
    #pragma unroll
    for (int i = 0; i < 8; ++i)
        s += g_partial[(b * 8 + i) * 512 + t];
    g_partial2[b * 512 + t] = s;
}

// ---------------- Stage 2 (s0): xbar, abar, bbar ----------------------------
__global__ void finalize_ab_k(const float* __restrict__ Wa,
                              const float* __restrict__ Wb) {
    __shared__ float sx[512];
    int t = threadIdx.x;
    float s = 0.f;
    #pragma unroll
    for (int p = 0; p < 32; ++p) s += g_partial2[p * 512 + t];
    s *= (1.0f / 32768.0f);
    sx[t] = s;
    __syncthreads();
    int w = t >> 5, lane = t & 31;
    const float* Wm = (w < 8) ? Wa : Wb;
    int r = w & 7;
    float acc = 0.f;
    #pragma unroll
    for (int q = 0; q < 16; ++q) {
        int i = lane + q * 32;
        acc += sx[i] * Wm[i * 8 + r];
    }
    #pragma unroll
    for (int off = 16; off; off >>= 1)
        acc += __shfl_xor_sync(0xffffffffu, acc, off);
    if (lane == 0) g_ab[w] = acc;
}

// ---------------- Stage A (s2): S dots, sign applied, NO ab scaling ---------
__global__ void compute_Sraw_k(const float* __restrict__ La,
                               const float* __restrict__ Ra,
                               const float* __restrict__ Rb) {
    int gw = (blockIdx.x * blockDim.x + threadIdx.x) >> 5;
    int lane = threadIdx.x & 31;
    if (gw >= 384) return;
    int k = gw >> 4, c = gw & 15;
    const float* Vk = (k < 8) ? La : ((k < 16) ? Ra : Rb);
    int kk = k & 7;
    const float* M = (c < 8) ? Ra : La;
    int r = c & 7;
    float acc = 0.f;
    #pragma unroll
    for (int q = 0; q < 16; ++q) {
        int i = lane + q * 32;
        acc += Vk[i * 8 + kk] * M[i * 8 + r];
    }
    #pragma unroll
    for (int off = 16; off; off >>= 1)
        acc += __shfl_xor_sync(0xffffffffu, acc, off);
    if (lane == 0)
        g_S[k * 16 + c] = (c < 8) ? -acc : acc;
    (void)r;
}

// ---------------- Stage B (s2): U0 dot products (warp per row) --------------
__global__ void f0dot_k(const float* __restrict__ U0,
                        const float* __restrict__ La,
                        const float* __restrict__ Ra) {
    int w = (blockIdx.x * blockDim.x + threadIdx.x) >> 5;   // row 0..1023
    int lane = threadIdx.x & 31;
    const float* u = U0 + (size_t)w * 512;
    float accA[8] = {0, 0, 0, 0, 0, 0, 0, 0};
    float accR[8] = {0, 0, 0, 0, 0, 0, 0, 0};
    #pragma unroll
    for (int q = 0; q < 16; ++q) {
        int i = lane + q * 32;
        float uv = u[i];
        float4 la0 = *(const float4*)(La + i * 8);
        float4 la1 = *(const float4*)(La + i * 8 + 4);
        float4 ra0 = *(const float4*)(Ra + i * 8);
        float4 ra1 = *(const float4*)(Ra + i * 8 + 4);
        accA[0] += uv * la0.x; accA[1] += uv * la0.y;
        accA[2] += uv * la0.z; accA[3] += uv * la0.w;
        accA[4] += uv * la1.x; accA[5] += uv * la1.y;
        accA[6] += uv * la1.z; accA[7] += uv * la1.w;
        accR[0] += uv * ra0.x; accR[1] += uv * ra0.y;
        accR[2] += uv * ra0.z; accR[3] += uv * ra0.w;
        accR[4] += uv * ra1.x; accR[5] += uv * ra1.y;
        accR[6] += uv * ra1.z; accR[7] += uv * ra1.w;
    }
    #pragma unroll
    for (int off = 16; off; off >>= 1) {
        #pragma unroll
        for (int r = 0; r < 8; ++r) {
            accA[r] += __shfl_xor_sync(0xffffffffu, accA[r], off);
            accR[r] += __shfl_xor_sync(0xffffffffu, accR[r], off);
        }
    }
    float outv = 0.f;
    #pragma unroll
    for (int r = 0; r < 8; ++r) {
        if (lane == r)     outv = accA[r];
        if (lane == r + 8) outv = accR[r];
    }
    if (lane < 16) g_F0d[w * 16 + lane] = outv;
}

// ---------------- Stage 3 (s0, post-join): RK4 in coefficient space ---------
__global__ void rk4_k(const float* __restrict__ Lb) {
    int row = (blockIdx.x * blockDim.x + threadIdx.x) >> 5;  // 0..1023
    int lane = threadIdx.x & 31;
    float f0 = 0.f;
    if (lane < 8)
        f0 = -g_ab[lane] * g_F0d[row * 16 + 8 + lane];
    else if (lane < 16)
        f0 = g_ab[lane - 8] * g_F0d[row * 16 + (lane - 8)];
    else if (lane < 24 && row >= 512)
        f0 = g_ab[8 + (lane - 16)] * Lb[(row - 512) * 8 + (lane - 16)];

    float scol[24];
    float dscale = g_ab[lane & 7];
    #pragma unroll
    for (int k = 0; k < 24; ++k)
        scol[k] = (lane < 16) ? g_S[k * 16 + lane] * dscale : 0.f;
    float p[24];
    #pragma unroll
    for (int k = 0; k < 24; ++k) p[k] = 0.f;
    const float dt = 1.0f / 8.0f;
    for (int step = 0; step < 8; ++step) {
        float v[24], acc[24];
        #pragma unroll
        for (int k = 0; k < 24; ++k) v[k] = p[k];
        float kc = f0;
        #pragma unroll
        for (int k = 0; k < 24; ++k) kc += v[k] * scol[k];
        #pragma unroll
        for (int k = 0; k < 24; ++k) {
            float kf = __shfl_sync(0xffffffffu, kc, k);
            acc[k] = kf;
            v[k] = p[k] + 0.5f * dt * kf;
        }
        kc = f0;
        #pragma unroll
        for (int k = 0; k < 24; ++k) kc += v[k] * scol[k];
        #pragma unroll
        for (int k = 0; k < 24; ++k) {
            float kf = __shfl_sync(0xffffffffu, kc, k);
            acc[k] += 2.0f * kf;
            v[k] = p[k] + 0.5f * dt * kf;
        }
        kc = f0;
        #pragma unroll
        for (int k = 0; k < 24; ++k) kc += v[k] * scol[k];
        #pragma unroll
        for (int k = 0; k < 24; ++k) {
            float kf = __shfl_sync(0xffffffffu, kc, k);
            acc[k] += 2.0f * kf;
            v[k] = p[k] + dt * kf;
        }
        kc = f0;
        #pragma unroll
        for (int k = 0; k < 24; ++k) kc += v[k] * scol[k];
        #pragma unroll
        for (int k = 0; k < 24; ++k) {
            float kf = __shfl_sync(0xffffffffu, kc, k);
            acc[k] += kf;
        }
        #pragma unroll
        for (int k = 0; k < 24; ++k) p[k] += (dt / 6.0f) * acc[k];
    }
    if (lane < 24) g_P[row * 24 + lane] = p[lane];
}

// ---------------- Stage 4 (s0): W = U0 + P V2^T  -> fp16 --------------------
__global__ void expand_W_k(const float* __restrict__ U0,
                           const float* __restrict__ La,
                           const float* __restrict__ Ra,
                           const float* __restrict__ Rb) {
    __shared__ float sP[8 * 24];
    int t = threadIdx.x;
    int o0 = blockIdx.x * 8;
    if (t < 192) sP[t] = g_P[o0 * 24 + t];
    __syncthreads();
    #pragma unroll
    for (int half = 0; half < 2; ++half) {
        int i = t + half * 256;
        float v2[24];
        float4 q;
        q = *(const float4*)(La + i * 8);
        v2[0] = q.x; v2[1] = q.y; v2[2] = q.z; v2[3] = q.w;
        q = *(const float4*)(La + i * 8 + 4);
        v2[4] = q.x; v2[5] = q.y; v2[6] = q.z; v2[7] = q.w;
        q = *(const float4*)(Ra + i * 8);
        v2[8] = q.x; v2[9] = q.y; v2[10] = q.z; v2[11] = q.w;
        q = *(const float4*)(Ra + i * 8 + 4);
        v2[12] = q.x; v2[13] = q.y; v2[14] = q.z; v2[15] = q.w;
        q = *(const float4*)(Rb + i * 8);
        v2[16] = q.x; v2[17] = q.y; v2[18] = q.z; v2[19] = q.w;
        q = *(const float4*)(Rb + i * 8 + 4);
        v2[20] = q.x; v2[21] = q.y; v2[22] = q.z; v2[23] = q.w;
        #pragma unroll
        for (int r = 0; r < 8; ++r) {
            float accv = U0[(size_t)(o0 + r) * 512 + i];
            #pragma unroll
            for (int k = 0; k < 24; ++k) accv += sP[r * 24 + k] * v2[k];
            g_W16[(size_t)(o0 + r) * 512 + i] = __float2half_rn(accv);
        }
    }
}

// ---------------- Stage 5 (s0): fp16 HMMA GEMM  out = x @ W^T ---------------
#define CP16(sa, ga) \
    asm volatile("cp.async.cg.shared.global [%0], [%1], 16;\n" :: "r"(sa), "l"(ga))

__device__ __forceinline__ void ldm_x4(uint32_t& r0, uint32_t& r1,
                                       uint32_t& r2, uint32_t& r3, uint32_t a) {
    asm volatile("ldmatrix.sync.aligned.m8n8.x4.shared.b16 {%0,%1,%2,%3}, [%4];"
                 : "=r"(r0), "=r"(r1), "=r"(r2), "=r"(r3) : "r"(a));
}

__device__ __forceinline__ void mma16816(float* c, const uint32_t* a,
                                         const uint32_t* b) {
    asm volatile(
        "mma.sync.aligned.m16n8k16.row.col.f32.f16.f16.f32 "
        "{%0,%1,%2,%3}, {%4,%5,%6,%7}, {%8,%9}, {%0,%1,%2,%3};"
        : "+f"(c[0]), "+f"(c[1]), "+f"(c[2]), "+f"(c[3])
        : "r"(a[0]), "r"(a[1]), "r"(a[2]), "r"(a[3]), "r"(b[0]), "r"(b[1]));
}

__global__ __launch_bounds__(256) void gemm_tc_k(float* __restrict__ out) {
    extern __shared__ __align__(16) char dynsm[];
    uint32_t base = (uint32_t)__cvta_generic_to_shared(dynsm);

    int tid = threadIdx.x;
    int lane = tid & 31;
    int w = tid >> 5;
    int wm = (w & 3) * 32;
    int wn = (w >> 2) * 64;
    int bm = blockIdx.y * 128;
    int bn = blockIdx.x * 128;

    float c[2][8][4];
    #pragma unroll
    for (int mi = 0; mi < 2; ++mi)
        #pragma unroll
        for (int ni = 0; ni < 8; ++ni)
            #pragma unroll
            for (int q = 0; q < 4; ++q) c[mi][ni][q] = 0.f;

    int lr0 = tid >> 2;
    int lu = tid & 3;

    auto issue_chunk = [&](int i) {
        int st = i % 3;
        uint32_t sA = base + st * 20480;
        uint32_t sB = sA + 10240;
        int ko = i << 5;
        #pragma unroll
        for (int j = 0; j < 2; ++j) {
            int r = lr0 + j * 64;
            const __half* ga = g_x16 + (size_t)(bm + r) * 512 + ko + lu * 8;
            CP16(sA + ((r * 5 + lu) << 4), ga);
            const __half* gb = g_W16 + (size_t)(bn + r) * 512 + ko + lu * 8;
            CP16(sB + ((r * 5 + lu) << 4), gb);
        }
        asm volatile("cp.async.commit_group;\n" ::);
    };

    issue_chunk(0);
    issue_chunk(1);

    int mg = lane >> 3, rr = lane & 7;

    for (int i = 0; i < 16; ++i) {
        if (i < 15) asm volatile("cp.async.wait_group 1;\n" ::);
        else        asm volatile("cp.async.wait_group 0;\n" ::);
        __syncthreads();
        if (i + 2 < 16) issue_chunk(i + 2);

        int st = i % 3;
        uint32_t sA = base + st * 20480;
        uint32_t sB = sA + 10240;
        #pragma unroll
        for (int ks = 0; ks < 2; ++ks) {
            uint32_t a[2][4];
            #pragma unroll
            for (int mi = 0; mi < 2; ++mi) {
                int row = wm + mi * 16 + (mg & 1) * 8 + rr;
                int ku = ks * 2 + (mg >> 1);
                ldm_x4(a[mi][0], a[mi][1], a[mi][2], a[mi][3],
                       sA + ((row * 5 + ku) << 4));
            }
            uint32_t b[8][2];
            #pragma unroll
            for (int j = 0; j < 4; ++j) {
                int row = wn + j * 16 + (mg >> 1) * 8 + rr;
                int ku = ks * 2 + (mg & 1);
                ldm_x4(b[2 * j][0], b[2 * j][1], b[2 * j + 1][0], b[2 * j + 1][1],
                       sB + ((row * 5 + ku) << 4));
            }
            #pragma unroll
            for (int mi = 0; mi < 2; ++mi)
                #pragma unroll
                for (int ni = 0; ni < 8; ++ni)
                    mma16816(c[mi][ni], a[mi], b[ni]);
        }
    }

    int gid = lane >> 2, tig = lane & 3;
    #pragma unroll
    for (int mi = 0; mi < 2; ++mi) {
        #pragma unroll
        for (int ni = 0; ni < 8; ++ni) {
            int row0 = bm + wm + mi * 16 + gid;
            int col = bn + wn + ni * 8 + tig * 2;
            float2* p0 = (float2*)(out + (size_t)row0 * 1024 + col);
            *p0 = make_float2(c[mi][ni][0], c[mi][ni][1]);
            float2* p1 = (float2*)(out + (size_t)(row0 + 8) * 1024 + col);
            *p1 = make_float2(c[mi][ni][2], c[mi][ni][3]);
        }
    }
}

// ---------------------------------------------------------------------------
extern "C" void kernel_launch(void* const* d_in, const int* in_sizes, int n_in,
                              void* d_out, int out_size) {
    const float* x  = (const float*)d_in[0];
    const float* U0 = (const float*)d_in[1];
    const float* Wa = (const float*)d_in[2];
    const float* La = (const float*)d_in[3];
    const float* Ra = (const float*)d_in[4];
    const float* Wb = (const float*)d_in[5];
    const float* Lb = (const float*)d_in[6];
    const float* Rb = (const float*)d_in[7];
    float* out = (float*)d_out;
    (void)in_sizes; (void)n_in; (void)out_size;

    static cudaStream_t s2 = nullptr;
    static cudaEvent_t eFork = nullptr, eJoin = nullptr;
    static int smem_set = 0;
    const int dyn_smem = 3 * 20480;      // 60 KB
    if (!smem_set) {
        cudaFuncSetAttribute(gemm_tc_k,
                             cudaFuncAttributeMaxDynamicSharedMemorySize,
                             dyn_smem);
        cudaStreamCreateWithFlags(&s2, cudaStreamNonBlocking);
        cudaEventCreateWithFlags(&eFork, cudaEventDisableTiming);
        cudaEventCreateWithFlags(&eJoin, cudaEventDisableTiming);
        smem_set = 1;
    }

    // fork: side stream runs x-independent dot kernels
    cudaEventRecord(eFork, 0);
    cudaStreamWaitEvent(s2, eFork, 0);
    compute_Sraw_k<<<48, 256, 0, s2>>>(La, Ra, Rb);
    f0dot_k<<<128, 256, 0, s2>>>(U0, La, Ra);
    cudaEventRecord(eJoin, s2);

    // main stream: x-dependent chain with tree-reduced xbar
    convert_reduce_k<<<256, 512>>>(x);
    reduce8_k<<<32, 512>>>();
    finalize_ab_k<<<1, 512>>>(Wa, Wb);

    // join, then the dependent tail
    cudaStreamWaitEvent(0, eJoin, 0);
    rk4_k<<<128, 256>>>(Lb);
    expand_W_k<<<128, 256>>>(U0, La, Ra, Rb);
    gemm_tc_k<<<dim3(8, 256), 256, dyn_smem>>>(out);
}